// round 8
// baseline (speedup 1.0000x reference)
#include <cuda_runtime.h>
#include <cuda_fp16.h>
#include <cstdint>
#include <cstddef>

// ---------------------------------------------------------------------------
// Problem constants
// ---------------------------------------------------------------------------
#define N_TOK   8192
#define DIN     4096
#define DOUT    4096
#define S_RANK  256
#define S_CAT   512

#define BM      128
#define BK      64          // 64 fp16 = 128B row (fp32: 256B row)
#define STAGES  3
#define THREADS 256

// GEMM1 smem layout (fused fp32->fp16 conversion)
#define A16_BYTES  (128 * 128)                 // 16384: fp16 A compute buffer
#define A32_ROWB   272                         // 256B data + 16B pad
#define A32_STAGE  (128 * A32_ROWB)            // 34816
#define B_STAGE    (128 * 128)                 // 16384
#define G1_SMEM    (A16_BYTES + STAGES * (A32_STAGE + B_STAGE))   // 169984

// GEMM2 (R5 winner config): 128x128, 3 stages fp16 A+B
#define G2_STAGE   (2 * 128 * 128)             // 32768
#define G2_SMEM    (STAGES * G2_STAGE)         // 98304

// ---------------------------------------------------------------------------
// Scratch (device globals; no runtime allocation)
// ---------------------------------------------------------------------------
__device__ __half g_B1[(size_t)S_CAT * DIN];     // sign(V)*v2*v1*u2   4 MB
__device__ __half g_B2[(size_t)DOUT * S_CAT];    // sign(U)*u1         4 MB
__device__ __half g_H [(size_t)N_TOK * S_CAT];   // H fp16             8 MB

// ---------------------------------------------------------------------------
// Helpers
// ---------------------------------------------------------------------------
__device__ __forceinline__ uint32_t smem_u32(const void* p) {
    uint32_t a;
    asm("{ .reg .u64 t; cvta.to.shared.u64 t, %1; cvt.u32.u64 %0, t; }" : "=r"(a) : "l"(p));
    return a;
}

#define SWZ(o) ((o) ^ (((o) >> 3) & 0x70))

#define CP_ASYNC16(s, g) \
    asm volatile("cp.async.cg.shared.global [%0], [%1], 16;" :: "r"(s), "l"(g))
#define CP_COMMIT() asm volatile("cp.async.commit_group;")
#define CP_WAIT(n)  asm volatile("cp.async.wait_group %0;" :: "n"(n) : "memory")

#define LDMATRIX_X4(r0, r1, r2, r3, addr)                                     \
    asm volatile("ldmatrix.sync.aligned.m8n8.x4.shared.b16 {%0,%1,%2,%3}, [%4];" \
        : "=r"(r0), "=r"(r1), "=r"(r2), "=r"(r3) : "r"(addr))

#define LDS128F(a, b, c, d, addr)                                             \
    asm volatile("ld.shared.v4.f32 {%0,%1,%2,%3}, [%4];"                      \
        : "=f"(a), "=f"(b), "=f"(c), "=f"(d) : "r"(addr))

#define STS128U(addr, a, b, c, d)                                             \
    asm volatile("st.shared.v4.b32 [%0], {%1,%2,%3,%4};"                      \
        :: "r"(addr), "r"(a), "r"(b), "r"(c), "r"(d))

#define MMA_16816(d, a, b0, b1)                                               \
    asm volatile("mma.sync.aligned.m16n8k16.row.col.f32.f16.f16.f32 "         \
        "{%0,%1,%2,%3}, {%4,%5,%6,%7}, {%8,%9}, {%0,%1,%2,%3};"               \
        : "+f"((d)[0]), "+f"((d)[1]), "+f"((d)[2]), "+f"((d)[3])              \
        : "r"((a)[0]), "r"((a)[1]), "r"((a)[2]), "r"((a)[3]), "r"(b0), "r"(b1))

__device__ __forceinline__ float sgn(float v) {
    return (v > 0.0f) ? 1.0f : ((v < 0.0f) ? -1.0f : 0.0f);
}

__device__ __forceinline__ uint32_t h2u(__half2 h) {
    return *reinterpret_cast<uint32_t*>(&h);
}

// ---------------------------------------------------------------------------
// Prep kernels (B matrices only; x conversion fused into GEMM1)
// ---------------------------------------------------------------------------
__global__ void prep_B1_kernel(const float* __restrict__ V,   const float* __restrict__ VR,
                               const float* __restrict__ v2,  const float* __restrict__ v2R,
                               const float* __restrict__ v1,  const float* __restrict__ v1R,
                               const float* __restrict__ u2,  const float* __restrict__ u2R) {
    int idx = blockIdx.x * blockDim.x + threadIdx.x;   // S_CAT*DIN
    int s = idx >> 12;
    int i = idx & 4095;
    float val;
    if (s < S_RANK) val = sgn(V [(size_t)s * DIN + i]) * v2[i] * v1[s] * u2[s];
    else {
        int s2 = s - S_RANK;
        val = sgn(VR[(size_t)s2 * DIN + i]) * v2R[i] * v1R[s2] * u2R[s2];
    }
    g_B1[idx] = __float2half(val);
}

__global__ void prep_B2_kernel(const float* __restrict__ U,  const float* __restrict__ UR,
                               const float* __restrict__ u1, const float* __restrict__ u1R) {
    int idx = blockIdx.x * blockDim.x + threadIdx.x;   // DOUT*S_CAT
    int j = idx >> 9;
    int s = idx & 511;
    float val;
    if (s < S_RANK) val = sgn(U [(size_t)j * S_RANK + s]) * u1[j];
    else            val = sgn(UR[(size_t)j * S_RANK + (s - S_RANK)]) * u1R[j];
    g_B2[idx] = __float2half(val);
}

// ---------------------------------------------------------------------------
// GEMM1: H[8192,512] = fp16(x[8192,4096]) @ B1[512,4096]^T
// A staged as fp32, converted smem->smem to fp16 each iteration.
// Register-double-buffered fragments. 1 CTA/SM.
// ---------------------------------------------------------------------------
__global__ __launch_bounds__(THREADS, 1) void gemm1_kernel(const float* __restrict__ x) {
    extern __shared__ char smem_raw[];
    const uint32_t sm16A = smem_u32(smem_raw);            // fp16 A buffer
    const uint32_t smA32 = sm16A + A16_BYTES;             // 3 fp32 A stages
    const uint32_t smB   = smA32 + STAGES * A32_STAGE;    // 3 fp16 B stages
    const int tid  = threadIdx.x;
    const int wid  = tid >> 5;
    const int lane = tid & 31;
    const int m0 = blockIdx.y * BM;
    const int n0 = blockIdx.x * 128;
    constexpr int NIT = DIN / BK;    // 64

    const int wm = wid >> 2;         // 0..1
    const int wn = wid & 3;          // 0..3

    const int ldRow = lane & 15;
    const int ldSel = lane >> 4;
    const uint32_t aOffBase = (uint32_t)((wm * 64 + ldRow) * 128 + ldSel * 16);
    const uint32_t bOffBase = (uint32_t)((wn * 32 + ldRow) * 128 + ldSel * 16);

    // conversion ownership: thread -> (row, half-of-row)
    const int cr = tid >> 1;
    const int ch = tid & 1;

    float acc[4][4][4] = {};

    auto load_stage = [&](int it) {
        const uint32_t a32b = smA32 + (it % STAGES) * A32_STAGE;
        const uint32_t bb   = smB   + (it % STAGES) * B_STAGE;
        const int k0 = it * BK;
        #pragma unroll
        for (int u = 0; u < 12; ++u) {
            int q = tid + u * THREADS;           // 0..3071
            if (q < 2048) {                      // A fp32: 128 rows x 16 chunks
                int row = q >> 4, c = q & 15;
                CP_ASYNC16(a32b + (uint32_t)(row * A32_ROWB + c * 16),
                           x + (size_t)(m0 + row) * DIN + k0 + c * 4);
            } else {                             // B fp16: 128 rows x 8 chunks
                int qb = q - 2048;
                int row = qb >> 3, c = qb & 7;
                CP_ASYNC16(bb + SWZ((uint32_t)(row * 128 + c * 16)),
                           g_B1 + (size_t)(n0 + row) * DIN + k0 + c * 8);
            }
        }
    };

    // Prologue
    load_stage(0); CP_COMMIT();
    load_stage(1); CP_COMMIT();

    #pragma unroll 1
    for (int it = 0; it < NIT; ++it) {
        CP_WAIT(1);
        __syncthreads();       // stage `it` resident; prior iter's sm16A reads done

        if (it + 2 < NIT) load_stage(it + 2);
        CP_COMMIT();

        // Convert fp32 A stage -> fp16 A buffer (each thread owns its span)
        {
            const uint32_t csrc = smA32 + (it % STAGES) * A32_STAGE
                                + (uint32_t)(cr * A32_ROWB + ch * 128);
            #pragma unroll
            for (int j = 0; j < 4; ++j) {
                float f0, f1, f2, f3, f4, f5, f6, f7;
                LDS128F(f0, f1, f2, f3, csrc + j * 32);
                LDS128F(f4, f5, f6, f7, csrc + j * 32 + 16);
                STS128U(sm16A + SWZ((uint32_t)(cr * 128 + ch * 64 + j * 16)),
                        h2u(__floats2half2_rn(f0, f1)), h2u(__floats2half2_rn(f2, f3)),
                        h2u(__floats2half2_rn(f4, f5)), h2u(__floats2half2_rn(f6, f7)));
            }
        }
        __syncthreads();       // fp16 A visible to all warps

        const uint32_t sB = smB + (it % STAGES) * B_STAGE;

        uint32_t af[2][4][4], bf[2][2][4];
        // preload ks=0 fragments
        #pragma unroll
        for (int i = 0; i < 4; ++i)
            LDMATRIX_X4(af[0][i][0], af[0][i][1], af[0][i][2], af[0][i][3],
                        sm16A + SWZ(aOffBase + (uint32_t)(i * 2048)));
        #pragma unroll
        for (int jj = 0; jj < 2; ++jj)
            LDMATRIX_X4(bf[0][jj][0], bf[0][jj][1], bf[0][jj][2], bf[0][jj][3],
                        sB + SWZ(bOffBase + (uint32_t)(jj * 2048)));

        #pragma unroll
        for (int ks = 0; ks < 4; ++ks) {
            const int cur = ks & 1, nxt = cur ^ 1;
            const int kpre = (ks < 3) ? (ks + 1) : ks;   // clamp: last prefetch is a no-op reload
            #pragma unroll
            for (int i = 0; i < 4; ++i)
                LDMATRIX_X4(af[nxt][i][0], af[nxt][i][1], af[nxt][i][2], af[nxt][i][3],
                            sm16A + SWZ(aOffBase + (uint32_t)(i * 2048 + kpre * 32)));
            #pragma unroll
            for (int jj = 0; jj < 2; ++jj)
                LDMATRIX_X4(bf[nxt][jj][0], bf[nxt][jj][1], bf[nxt][jj][2], bf[nxt][jj][3],
                            sB + SWZ(bOffBase + (uint32_t)(jj * 2048 + kpre * 32)));
            #pragma unroll
            for (int i = 0; i < 4; ++i)
                #pragma unroll
                for (int j = 0; j < 4; ++j)
                    MMA_16816(acc[i][j], af[cur][i],
                              bf[cur][j >> 1][(j & 1)], bf[cur][j >> 1][(j & 1) + 2]);
        }
    }

    // Epilogue: store H fp16
    const int rBase = m0 + wm * 64 + (lane >> 2);
    const int cBase = n0 + wn * 32 + (lane & 3) * 2;
    #pragma unroll
    for (int i = 0; i < 4; ++i) {
        const int r = rBase + i * 16;
        #pragma unroll
        for (int j = 0; j < 4; ++j) {
            const int c = cBase + j * 8;
            *(__half2*)&g_H[(size_t)r * S_CAT + c] =
                __floats2half2_rn(acc[i][j][0], acc[i][j][1]);
            *(__half2*)&g_H[(size_t)(r + 8) * S_CAT + c] =
                __floats2half2_rn(acc[i][j][2], acc[i][j][3]);
        }
    }
}

// ---------------------------------------------------------------------------
// GEMM2 (R5 winner): y[8192,4096] = H @ B2^T + bias. 128x128, 2 CTAs/SM.
// ---------------------------------------------------------------------------
__global__ __launch_bounds__(THREADS, 2) void gemm2_kernel(float* __restrict__ out,
                                                           const float* __restrict__ bias) {
    extern __shared__ char smem_raw[];
    const uint32_t sm_tiles = smem_u32(smem_raw);
    const int tid  = threadIdx.x;
    const int wid  = tid >> 5;
    const int lane = tid & 31;
    const int m0 = blockIdx.y * BM;
    const int n0 = blockIdx.x * 128;
    constexpr int K   = S_CAT;
    constexpr int NIT = K / BK;      // 8
    constexpr int STAGE_A = BM * 128;

    const int wm = wid >> 2;
    const int wn = wid & 3;

    const int ldRow = lane & 15;
    const int ldSel = lane >> 4;
    const uint32_t aOffBase = (uint32_t)((wm * 64 + ldRow) * 128 + ldSel * 16);
    const uint32_t bOffBase = (uint32_t)((wn * 32 + ldRow) * 128 + ldSel * 16);

    float acc[4][4][4] = {};

    auto load_stage = [&](int it) {
        const uint32_t sbase = sm_tiles + (it % STAGES) * G2_STAGE;
        const int k0 = it * BK;
        #pragma unroll
        for (int u = 0; u < 8; ++u) {
            int q = tid + u * THREADS;
            if (q < 1024) {
                int row = q >> 3, c = q & 7;
                CP_ASYNC16(sbase + SWZ((uint32_t)(row * 128 + c * 16)),
                           g_H + (size_t)(m0 + row) * K + k0 + c * 8);
            } else {
                int qb = q - 1024;
                int row = qb >> 3, c = qb & 7;
                CP_ASYNC16(sbase + STAGE_A + SWZ((uint32_t)(row * 128 + c * 16)),
                           g_B2 + (size_t)(n0 + row) * K + k0 + c * 8);
            }
        }
    };

    load_stage(0); CP_COMMIT();
    load_stage(1); CP_COMMIT();

    #pragma unroll 1
    for (int it = 0; it < NIT; ++it) {
        CP_WAIT(1);
        __syncthreads();

        if (it + 2 < NIT) load_stage(it + 2);
        CP_COMMIT();

        const uint32_t sA = sm_tiles + (it % STAGES) * G2_STAGE;
        const uint32_t sB = sA + STAGE_A;

        #pragma unroll
        for (int ks = 0; ks < 4; ++ks) {
            uint32_t af[4][4], bf[2][4];
            #pragma unroll
            for (int i = 0; i < 4; ++i)
                LDMATRIX_X4(af[i][0], af[i][1], af[i][2], af[i][3],
                            sA + SWZ(aOffBase + (uint32_t)(i * 2048 + ks * 32)));
            #pragma unroll
            for (int jj = 0; jj < 2; ++jj)
                LDMATRIX_X4(bf[jj][0], bf[jj][1], bf[jj][2], bf[jj][3],
                            sB + SWZ(bOffBase + (uint32_t)(jj * 2048 + ks * 32)));
            #pragma unroll
            for (int i = 0; i < 4; ++i)
                #pragma unroll
                for (int j = 0; j < 4; ++j)
                    MMA_16816(acc[i][j], af[i], bf[j >> 1][(j & 1)], bf[j >> 1][(j & 1) + 2]);
        }
    }

    const int rBase = m0 + wm * 64 + (lane >> 2);
    const int cBase = n0 + wn * 32 + (lane & 3) * 2;
    #pragma unroll
    for (int i = 0; i < 4; ++i) {
        const int r = rBase + i * 16;
        #pragma unroll
        for (int j = 0; j < 4; ++j) {
            const int c = cBase + j * 8;
            const float b0 = bias[c], b1 = bias[c + 1];
            float2 v0 = make_float2(acc[i][j][0] + b0, acc[i][j][1] + b1);
            float2 v1 = make_float2(acc[i][j][2] + b0, acc[i][j][3] + b1);
            *(float2*)&out[(size_t)r * DOUT + c] = v0;
            *(float2*)&out[(size_t)(r + 8) * DOUT + c] = v1;
        }
    }
}

// ---------------------------------------------------------------------------
// Launch
// ---------------------------------------------------------------------------
extern "C" void kernel_launch(void* const* d_in, const int* in_sizes, int n_in,
                              void* d_out, int out_size) {
    const float* x    = (const float*)d_in[0];
    const float* V    = (const float*)d_in[1];
    const float* U    = (const float*)d_in[2];
    const float* v1   = (const float*)d_in[3];
    const float* v2   = (const float*)d_in[4];
    const float* u1   = (const float*)d_in[5];
    const float* u2   = (const float*)d_in[6];
    const float* V_R  = (const float*)d_in[7];
    const float* U_R  = (const float*)d_in[8];
    const float* v1_R = (const float*)d_in[9];
    const float* v2_R = (const float*)d_in[10];
    const float* u1_R = (const float*)d_in[11];
    const float* u2_R = (const float*)d_in[12];
    const float* bias = (const float*)d_in[13];
    float* out = (float*)d_out;

    cudaFuncSetAttribute(gemm1_kernel, cudaFuncAttributeMaxDynamicSharedMemorySize, G1_SMEM);
    cudaFuncSetAttribute(gemm2_kernel, cudaFuncAttributeMaxDynamicSharedMemorySize, G2_SMEM);

    prep_B1_kernel<<<(S_CAT * DIN) / 256, 256>>>(V, V_R, v2, v2_R, v1, v1_R, u2, u2_R);
    prep_B2_kernel<<<(DOUT * S_CAT) / 256, 256>>>(U, U_R, u1, u1_R);

    // GEMM1: grid (4, 64) = 256 CTAs, 1/SM
    gemm1_kernel<<<dim3(S_CAT / 128, N_TOK / BM), THREADS, G1_SMEM>>>(x);

    // GEMM2: grid (32, 64) = 2048 CTAs, 2/SM
    gemm2_kernel<<<dim3(DOUT / 128, N_TOK / BM), THREADS, G2_SMEM>>>(out, bias);
}